// round 13
// baseline (speedup 1.0000x reference)
#include <cuda_runtime.h>
#include <cstdint>

#define N_CATS 8
#define NBLOCKS 592            // 4 CTAs/SM * 148 SMs
#define NTHREADS 256
#define NWARPS_TOTAL (NBLOCKS * (NTHREADS / 32))

// Device-global scratch: 8x8 confusion-matrix counts + arrival ticket.
__device__ unsigned int g_cm[64];
__device__ unsigned int g_done;

// Ballot-histogram one 32-element block; per-lane (pred, tv, valid).
__device__ __forceinline__ void vote32(
    unsigned bin, bool v, const unsigned* __restrict__ sgn,
    unsigned& cL, unsigned& cH)
{
    unsigned m = __ballot_sync(0xffffffffu, v);
    #pragma unroll
    for (int k = 0; k < 5; k++) {
        unsigned mb = __ballot_sync(0xffffffffu, (bin >> k) & 1u);
        m &= mb ^ sgn[k];
    }
    unsigned mb5 = __ballot_sync(0xffffffffu, (bin >> 5) & 1u);
    cL += __popc(m & ~mb5);
    cH += __popc(m & mb5);
}

// Combine own + partner float4 argmax into the element's 8-way argmax.
// Even lane finalizes the A element; odd lane the B element.
__device__ __forceinline__ int pair_argmax(
    float4 A, float4 B, int lane)
{
    int aA = 0; float mA = A.x;
    if (A.y > mA) { mA = A.y; aA = 1; }
    if (A.z > mA) { mA = A.z; aA = 2; }
    if (A.w > mA) { mA = A.w; aA = 3; }
    int aB = 0; float mB = B.x;
    if (B.y > mB) { mB = B.y; aB = 1; }
    if (B.z > mB) { mB = B.z; aB = 2; }
    if (B.w > mB) { mB = B.w; aB = 3; }

    float mAp = __shfl_xor_sync(0xffffffffu, mA, 1);
    int   aAp = __shfl_xor_sync(0xffffffffu, aA, 1);
    float mBp = __shfl_xor_sync(0xffffffffu, mB, 1);
    int   aBp = __shfl_xor_sync(0xffffffffu, aB, 1);

    // Even lane: own A = cats 0-3, partner A = cats 4-7 (hi wins on strict >).
    // Odd lane:  partner B = cats 0-3, own B = cats 4-7.
    if (lane & 1) return (mB  > mBp) ? (4 + aB)  : aBp;
    else          return (mAp > mA ) ? (4 + aAp) : aA;
}

__global__ __launch_bounds__(NTHREADS, 4) void qwk_fused_kernel(
    const float4* __restrict__ logits4,   // 2 float4 per element
    const int* __restrict__ targets,      // int32
    float* __restrict__ out,
    int n_elems)                          // B*S, multiple of 64
{
    __shared__ unsigned int s_cm[64];
    __shared__ bool s_is_last;
    const int tid = threadIdx.x;
    const int lane = tid & 31;
    if (tid < 64) s_cm[tid] = 0u;
    __syncthreads();

    // Loop-invariant sign masks for this lane's two bins (lane, lane+32).
    unsigned sgn[5];
    #pragma unroll
    for (int k = 0; k < 5; k++)
        sgn[k] = (((unsigned)lane >> k) & 1u) - 1u;   // bit=1 -> 0x0, bit=0 -> ~0

    unsigned cL = 0u, cH = 0u;

    const int warp_global = blockIdx.x * (NTHREADS / 32) + (tid >> 5);
    const int stride = NWARPS_TOTAL * 64;              // elements per grid step
    const int pair = lane >> 1;                        // element index within 16-group

    int E = warp_global * 64;
    if (E >= n_elems) goto flush;

    {
        // Prefetch targets for the first iteration.
        // Block 0 (elements E..E+31):  A-half elements E+pair,    B-half E+16+pair
        // Block 1 (elements E+32..63): A-half elements E+32+pair, B-half E+48+pair
        int tA0 = __ldcs(targets + E +      pair);
        int tB0 = __ldcs(targets + E + 16 + pair);
        int tA1 = __ldcs(targets + E + 32 + pair);
        int tB1 = __ldcs(targets + E + 48 + pair);

        for (; E < n_elems; ) {
            int En = E + stride;
            bool have_next = (En < n_elems);
            int Ec = have_next ? En : E;   // clamp for safe prefetch
            // Prefetch next iteration's targets (independent of this iter).
            int nA0 = __ldcs(targets + Ec +      pair);
            int nB0 = __ldcs(targets + Ec + 16 + pair);
            int nA1 = __ldcs(targets + Ec + 32 + pair);
            int nB1 = __ldcs(targets + Ec + 48 + pair);

            bool vA0 = ((unsigned)(tA0 - 1) < 7u);
            bool vB0 = ((unsigned)(tB0 - 1) < 7u);
            bool vA1 = ((unsigned)(tA1 - 1) < 7u);
            bool vB1 = ((unsigned)(tB1 - 1) < 7u);

            const float4* p = logits4 + (size_t)2 * E;
            // Predicated dense loads: whole 32B sector skipped when the
            // element's target == 0 (both lanes of the pair share the pred).
            float4 A0 = make_float4(0.f, 0.f, 0.f, 0.f);
            float4 B0 = A0, A1 = A0, B1 = A0;
            if (vA0) A0 = __ldcs(p +       lane);
            if (vB0) B0 = __ldcs(p + 32 +  lane);
            if (vA1) A1 = __ldcs(p + 64 +  lane);
            if (vB1) B1 = __ldcs(p + 96 +  lane);

            // Block 0
            {
                int pred = pair_argmax(A0, B0, lane);
                int tv   = (lane & 1) ? tB0 : tA0;
                bool v   = (lane & 1) ? vB0 : vA0;
                vote32((unsigned)tv * 8u + (unsigned)pred, v, sgn, cL, cH);
            }
            // Block 1
            {
                int pred = pair_argmax(A1, B1, lane);
                int tv   = (lane & 1) ? tB1 : tA1;
                bool v   = (lane & 1) ? vB1 : vA1;
                vote32((unsigned)tv * 8u + (unsigned)pred, v, sgn, cL, cH);
            }

            tA0 = nA0; tB0 = nB0; tA1 = nA1; tB1 = nB1;
            E = En;
            if (!have_next) break;
        }
    }

flush:
    // Per-warp flush: 2 shared atomics per lane, once per kernel.
    if (cL) atomicAdd(&s_cm[lane], cL);
    if (cH) atomicAdd(&s_cm[lane + 32], cH);
    __syncthreads();

    // Block flush to global.
    if (tid < 64) {
        unsigned int c = s_cm[tid];
        if (c) atomicAdd(&g_cm[tid], c);
    }

    // Ticket: last block to arrive finalizes.
    __threadfence();
    __syncthreads();
    if (tid == 0) {
        unsigned int rank = atomicAdd(&g_done, 1u);
        s_is_last = (rank == gridDim.x - 1);
    }
    __syncthreads();
    if (!s_is_last) return;

    if (tid == 0) {
        __threadfence();  // acquire: see all blocks' g_cm atomics

        float cm[64];
        float n = 0.0f;
        #pragma unroll
        for (int i = 0; i < 64; i++) {
            unsigned int c = atomicAdd(&g_cm[i], 0u);   // coherent read
            cm[i] = (float)c;
            n += cm[i];
        }

        float loss;
        if (n == 0.0f) {
            loss = 0.0f;   // qwk = 1 -> loss 0
        } else {
            float inv_n = 1.0f / n;
            #pragma unroll
            for (int i = 0; i < 64; i++) cm[i] *= inv_n;

            float mt[8], mp[8];
            #pragma unroll
            for (int i = 0; i < 8; i++) { mt[i] = 0.0f; mp[i] = 0.0f; }
            #pragma unroll
            for (int i = 0; i < 8; i++)
                #pragma unroll
                for (int jj = 0; jj < 8; jj++) {
                    mt[i] += cm[i * 8 + jj];
                    mp[jj] += cm[i * 8 + jj];
                }

            const float inv_d2 = 1.0f / 49.0f;
            float num = 0.0f, den = 0.0f;
            #pragma unroll
            for (int i = 0; i < 8; i++)
                #pragma unroll
                for (int jj = 0; jj < 8; jj++) {
                    float d = (float)(i - jj);
                    float w = 1.0f - d * d * inv_d2;
                    num += w * cm[i * 8 + jj];
                    den += w * mt[i] * mp[jj];
                }

            float qwk = (den == 0.0f) ? 0.0f : (num / den);
            loss = 1.0f - qwk;
        }
        out[0] = loss;

        // Reset scratch for the next graph replay.
        #pragma unroll
        for (int i = 0; i < 64; i++) g_cm[i] = 0u;
        g_done = 0u;
        __threadfence();
    }
}

extern "C" void kernel_launch(void* const* d_in, const int* in_sizes, int n_in,
                              void* d_out, int out_size) {
    const float4* logits4 = (const float4*)d_in[0];
    const int* targets = (const int*)d_in[1];
    float* out = (float*)d_out;
    int n_elems = in_sizes[1];       // 2048*4096, multiple of 64

    qwk_fused_kernel<<<NBLOCKS, NTHREADS>>>(logits4, targets, out, n_elems);
}